// round 1
// baseline (speedup 1.0000x reference)
#include <cuda_runtime.h>
#include <math.h>

// Problem constants
#define TT   4096           // tokens (2*2048)
#define HH   1024           // hidden
#define DD   2752           // intermediate
#define NE   8              // routed experts
#define KEXP 2              // top-k
#define BM   64
#define BN   64
#define BKK  16
#define ROWCAP (TT*KEXP + NE*BM)   // 8704 padded routed rows

// ---------------- scratch (device globals; allocation-free) ----------------
__device__ int   g_counts[NE];
__device__ int   g_cursor[NE];
__device__ int   g_offsets[NE+1];
__device__ int   g_row_token[ROWCAP];    // padded row -> token (-1 = pad)
__device__ int   g_row_tk[ROWCAP];       // padded row -> t*2+k
__device__ int   g_tok_e[TT*KEXP];       // token,k -> expert
__device__ float g_tok_w[TT*KEXP];       // token,k -> renormalized weight
__device__ float g_hid [(size_t)ROWCAP*DD];   // routed hidden (silu(g)*u)
__device__ float g_shid[(size_t)TT*DD];       // shared-expert hidden
__device__ float g_eo  [(size_t)TT*KEXP*HH];  // routed down outputs per (t,k)

// ---------------- init ----------------
__global__ void init_kernel() {
    int i = blockIdx.x * blockDim.x + threadIdx.x;
    if (i < NE) { g_counts[i] = 0; g_cursor[i] = 0; }
    if (i < ROWCAP) g_row_token[i] = -1;
}

// ---------------- routing: logits -> softmax -> top2 -> counts ----------------
__global__ void route_kernel(const float* __restrict__ x,
                             const float* __restrict__ gw) {
    int t    = blockIdx.x * (blockDim.x >> 5) + (threadIdx.x >> 5);
    int lane = threadIdx.x & 31;
    if (t >= TT) return;
    const float* xr = x + (size_t)t * HH;

    float xs[HH/32];
    #pragma unroll
    for (int i = 0; i < HH/32; i++) xs[i] = xr[lane + 32*i];

    float logit[NE];
    #pragma unroll
    for (int e = 0; e < NE; e++) {
        const float* w = gw + e * HH;
        float s = 0.f;
        #pragma unroll
        for (int i = 0; i < HH/32; i++) s += xs[i] * w[lane + 32*i];
        #pragma unroll
        for (int o = 16; o; o >>= 1) s += __shfl_xor_sync(0xffffffffu, s, o);
        logit[e] = s;
    }

    float m = logit[0];
    #pragma unroll
    for (int e = 1; e < NE; e++) m = fmaxf(m, logit[e]);
    float p[NE], ssum = 0.f;
    #pragma unroll
    for (int e = 0; e < NE; e++) { p[e] = expf(logit[e] - m); ssum += p[e]; }
    float inv = 1.f / ssum;
    #pragma unroll
    for (int e = 0; e < NE; e++) p[e] *= inv;

    int i0 = 0;
    #pragma unroll
    for (int e = 1; e < NE; e++) if (p[e] > p[i0]) i0 = e;
    int i1 = -1;
    #pragma unroll
    for (int e = 0; e < NE; e++)
        if (e != i0 && (i1 < 0 || p[e] > p[i1])) i1 = e;

    float w0 = p[i0], w1 = p[i1];
    float norm = 1.f / (w0 + w1 + 1e-20f);
    w0 *= norm; w1 *= norm;

    if (lane == 0) {
        g_tok_e[t*2]   = i0;  g_tok_e[t*2+1] = i1;
        g_tok_w[t*2]   = w0;  g_tok_w[t*2+1] = w1;
        atomicAdd(&g_counts[i0], 1);
        atomicAdd(&g_counts[i1], 1);
    }
}

// ---------------- scan: BM-padded expert segment offsets ----------------
__global__ void scan_kernel() {
    if (threadIdx.x == 0 && blockIdx.x == 0) {
        int off = 0;
        for (int e = 0; e < NE; e++) {
            g_offsets[e] = off;
            off += ((g_counts[e] + BM - 1) / BM) * BM;
        }
        g_offsets[NE] = off;
    }
}

// ---------------- assign tokens to expert rows ----------------
__global__ void assign_kernel() {
    int idx = blockIdx.x * blockDim.x + threadIdx.x;
    if (idx >= TT*KEXP) return;
    int e   = g_tok_e[idx];
    int pos = atomicAdd(&g_cursor[e], 1);
    int row = g_offsets[e] + pos;
    g_row_token[row] = idx >> 1;
    g_row_tk[row]    = idx;
}

// ---------------- gate+up GEMM, silu epilogue ----------------
// out = silu(X @ Wg) * (X @ Wu), rows grouped by expert (ROUTED) or identity.
template<bool ROUTED>
__global__ void gateup_kernel(const float* __restrict__ X,
                              const float* __restrict__ Wg_base,
                              const float* __restrict__ Wu_base) {
    __shared__ float As[BKK][BM];
    __shared__ float Bg[BKK][BN];
    __shared__ float Bu[BKK][BN];
    __shared__ int   Rtok[BM];

    int row0 = blockIdx.y * BM;
    int n0   = blockIdx.x * BN;

    const float *Wg, *Wu;
    float* outp;
    if (ROUTED) {
        if (row0 >= g_offsets[NE]) return;
        int e = 0;
        #pragma unroll
        for (int i = 1; i < NE; i++) if (row0 >= g_offsets[i]) e = i;
        Wg = Wg_base + (size_t)e * HH * DD;
        Wu = Wu_base + (size_t)e * HH * DD;
        outp = g_hid;
    } else {
        Wg = Wg_base; Wu = Wu_base; outp = g_shid;
    }

    int tid = threadIdx.x;
    if (tid < BM) Rtok[tid] = ROUTED ? g_row_token[row0 + tid] : (row0 + tid);
    __syncthreads();

    int tm = tid >> 4, tn = tid & 15;
    float accg[8][4], accu[8][4];
    #pragma unroll
    for (int i = 0; i < 8; i++)
        #pragma unroll
        for (int j = 0; j < 4; j++) { accg[i][j] = 0.f; accu[i][j] = 0.f; }

    for (int h0 = 0; h0 < HH; h0 += BKK) {
        #pragma unroll
        for (int rep = 0; rep < 2; rep++) {
            int li = tid + rep * 128;            // 0..255
            int r = li >> 2, c4 = li & 3;
            int tok = Rtok[r]; if (tok < 0) tok = 0;
            float4 v = *(const float4*)(X + (size_t)tok * HH + h0 + c4 * 4);
            As[c4*4+0][r] = v.x; As[c4*4+1][r] = v.y;
            As[c4*4+2][r] = v.z; As[c4*4+3][r] = v.w;
        }
        #pragma unroll
        for (int rep = 0; rep < 2; rep++) {
            int li = tid + rep * 128;
            int kr = li >> 4, c = (li & 15) * 4;
            *(float4*)&Bg[kr][c] = *(const float4*)(Wg + (size_t)(h0+kr) * DD + n0 + c);
            *(float4*)&Bu[kr][c] = *(const float4*)(Wu + (size_t)(h0+kr) * DD + n0 + c);
        }
        __syncthreads();
        #pragma unroll
        for (int kk = 0; kk < BKK; kk++) {
            float a[8], bg[4], bu[4];
            *(float4*)(a)     = *(float4*)&As[kk][tm*8];
            *(float4*)(a + 4) = *(float4*)&As[kk][tm*8+4];
            *(float4*)bg = *(float4*)&Bg[kk][tn*4];
            *(float4*)bu = *(float4*)&Bu[kk][tn*4];
            #pragma unroll
            for (int i = 0; i < 8; i++)
                #pragma unroll
                for (int j = 0; j < 4; j++) {
                    accg[i][j] += a[i] * bg[j];
                    accu[i][j] += a[i] * bu[j];
                }
        }
        __syncthreads();
    }

    #pragma unroll
    for (int i = 0; i < 8; i++) {
        int r = tm * 8 + i;
        if (ROUTED && Rtok[r] < 0) continue;
        float4 hv;
        float g, u;
        g = accg[i][0]; u = accu[i][0]; hv.x = g / (1.f + expf(-g)) * u;
        g = accg[i][1]; u = accu[i][1]; hv.y = g / (1.f + expf(-g)) * u;
        g = accg[i][2]; u = accu[i][2]; hv.z = g / (1.f + expf(-g)) * u;
        g = accg[i][3]; u = accu[i][3]; hv.w = g / (1.f + expf(-g)) * u;
        *(float4*)(outp + (size_t)(row0 + r) * DD + n0 + tn * 4) = hv;
    }
}

// ---------------- down GEMM ----------------
// ROUTED: g_eo[tk] = hid_row @ we_down[e]
// !ROUTED: out[t]  = shid[t] @ sw_down + w0*eo[t,0] + w1*eo[t,1]
template<bool ROUTED>
__global__ void down_kernel(const float* __restrict__ Wd_base,
                            float* __restrict__ d_out) {
    __shared__ float As[BKK][BM];
    __shared__ float Bs[BKK][BN];
    __shared__ int   Rinfo[BM];

    int row0 = blockIdx.y * BM;
    int n0   = blockIdx.x * BN;

    const float *A, *Wd;
    if (ROUTED) {
        if (row0 >= g_offsets[NE]) return;
        int e = 0;
        #pragma unroll
        for (int i = 1; i < NE; i++) if (row0 >= g_offsets[i]) e = i;
        Wd = Wd_base + (size_t)e * DD * HH;
        A  = g_hid;
    } else {
        Wd = Wd_base;
        A  = g_shid;
    }

    int tid = threadIdx.x;
    if (tid < BM) {
        if (ROUTED) {
            int tok = g_row_token[row0 + tid];
            Rinfo[tid] = (tok < 0) ? -1 : g_row_tk[row0 + tid];
        } else {
            Rinfo[tid] = row0 + tid;
        }
    }
    __syncthreads();

    int tm = tid >> 4, tn = tid & 15;
    float acc[8][4];
    #pragma unroll
    for (int i = 0; i < 8; i++)
        #pragma unroll
        for (int j = 0; j < 4; j++) acc[i][j] = 0.f;

    for (int h0 = 0; h0 < DD; h0 += BKK) {
        #pragma unroll
        for (int rep = 0; rep < 2; rep++) {
            int li = tid + rep * 128;
            int r = li >> 2, c4 = li & 3;
            float4 v = *(const float4*)(A + (size_t)(row0 + r) * DD + h0 + c4 * 4);
            As[c4*4+0][r] = v.x; As[c4*4+1][r] = v.y;
            As[c4*4+2][r] = v.z; As[c4*4+3][r] = v.w;
        }
        #pragma unroll
        for (int rep = 0; rep < 2; rep++) {
            int li = tid + rep * 128;
            int kr = li >> 4, c = (li & 15) * 4;
            *(float4*)&Bs[kr][c] = *(const float4*)(Wd + (size_t)(h0+kr) * HH + n0 + c);
        }
        __syncthreads();
        #pragma unroll
        for (int kk = 0; kk < BKK; kk++) {
            float a[8], b[4];
            *(float4*)(a)     = *(float4*)&As[kk][tm*8];
            *(float4*)(a + 4) = *(float4*)&As[kk][tm*8+4];
            *(float4*)b = *(float4*)&Bs[kk][tn*4];
            #pragma unroll
            for (int i = 0; i < 8; i++)
                #pragma unroll
                for (int j = 0; j < 4; j++)
                    acc[i][j] += a[i] * b[j];
        }
        __syncthreads();
    }

    #pragma unroll
    for (int i = 0; i < 8; i++) {
        int r = tm * 8 + i;
        int info = Rinfo[r];
        if (ROUTED) {
            if (info < 0) continue;
            float4 v; v.x = acc[i][0]; v.y = acc[i][1]; v.z = acc[i][2]; v.w = acc[i][3];
            *(float4*)(g_eo + (size_t)info * HH + n0 + tn * 4) = v;
        } else {
            int t = info;
            float w0 = g_tok_w[t*2], w1 = g_tok_w[t*2+1];
            const float* e0 = g_eo + (size_t)(t*2)   * HH + n0 + tn * 4;
            const float* e1 = g_eo + (size_t)(t*2+1) * HH + n0 + tn * 4;
            float4 v0 = *(const float4*)e0;
            float4 v1 = *(const float4*)e1;
            float4 o;
            o.x = acc[i][0] + w0 * v0.x + w1 * v1.x;
            o.y = acc[i][1] + w0 * v0.y + w1 * v1.y;
            o.z = acc[i][2] + w0 * v0.z + w1 * v1.z;
            o.w = acc[i][3] + w0 * v0.w + w1 * v1.w;
            *(float4*)(d_out + (size_t)t * HH + n0 + tn * 4) = o;
        }
    }
}

// ---------------- launch ----------------
extern "C" void kernel_launch(void* const* d_in, const int* in_sizes, int n_in,
                              void* d_out, int out_size) {
    const float* x       = (const float*)d_in[0];
    const float* gate_w  = (const float*)d_in[1];
    const float* we_gate = (const float*)d_in[2];
    const float* we_up   = (const float*)d_in[3];
    const float* we_down = (const float*)d_in[4];
    const float* sw_gate = (const float*)d_in[5];
    const float* sw_up   = (const float*)d_in[6];
    const float* sw_down = (const float*)d_in[7];
    float* out = (float*)d_out;

    init_kernel<<<(ROWCAP + 255) / 256, 256>>>();
    route_kernel<<<TT / 8, 256>>>(x, gate_w);
    scan_kernel<<<1, 32>>>();
    assign_kernel<<<(TT * KEXP + 255) / 256, 256>>>();

    dim3 blk(128);
    gateup_kernel<true ><<<dim3(DD / BN, ROWCAP / BM), blk>>>(x, we_gate, we_up);
    gateup_kernel<false><<<dim3(DD / BN, TT / BM),     blk>>>(x, sw_gate, sw_up);
    down_kernel<true ><<<dim3(HH / BN, ROWCAP / BM), blk>>>(we_down, out);
    down_kernel<false><<<dim3(HH / BN, TT / BM),     blk>>>(sw_down, out);
}